// round 5
// baseline (speedup 1.0000x reference)
#include <cuda_runtime.h>
#include <cuda_bf16.h>
#include <math.h>
#include <stdint.h>

// ============================================================================
// MoE (T=8192, D=1024, H=4096, O=1024, E=8, top-2)
// mma.sync m16n8k16 bf16 with 2-way operand split (3 MMAs) ~ fp32 accuracy.
// All fp32->bf16(hi,lo) splits precomputed to global planes; GEMM producers are
// pure cp.async copies into a 3-stage smem pipeline. Plain sm_103 PTX only.
// ============================================================================

#define NTOK   8192
#define DMODEL 1024
#define DHID   4096
#define DOUT   1024
#define NEXP   8
#define MAXROWS (NTOK * 2)

// -------------------- device scratch (no allocs allowed) --------------------
__device__ int   g_count[NEXP];
__device__ int   g_base[NEXP];
__device__ float g_probsum[NEXP];
__device__ int   g_token[NEXP * NTOK];
__device__ int   g_ae[NTOK * 2];
__device__ int   g_ap[NTOK * 2];
__device__ float g_aw[NTOK * 2];

__device__ __nv_bfloat16 g_xh[(size_t)NTOK * DMODEL];
__device__ __nv_bfloat16 g_xl[(size_t)NTOK * DMODEL];
__device__ __nv_bfloat16 g_w1h[(size_t)NEXP * DHID * DMODEL];
__device__ __nv_bfloat16 g_w1l[(size_t)NEXP * DHID * DMODEL];
__device__ __nv_bfloat16 g_w2h[(size_t)NEXP * DOUT * DHID];
__device__ __nv_bfloat16 g_w2l[(size_t)NEXP * DOUT * DHID];
__device__ __nv_bfloat16 g_hh[(size_t)MAXROWS * DHID];
__device__ __nv_bfloat16 g_hl[(size_t)MAXROWS * DHID];
__device__ float         g_y [(size_t)MAXROWS * DOUT];

// -------------------- helpers --------------------
__device__ __forceinline__ uint32_t smem_u32(const void* p) {
    uint32_t a;
    asm("{ .reg .u64 t; cvta.to.shared.u64 t, %1; cvt.u32.u64 %0, t; }"
        : "=r"(a) : "l"(p));
    return a;
}

__device__ __forceinline__ void ldsm4(uint32_t* r, uint32_t addr) {
    asm volatile("ldmatrix.sync.aligned.m8n8.x4.shared.b16 {%0,%1,%2,%3}, [%4];"
                 : "=r"(r[0]), "=r"(r[1]), "=r"(r[2]), "=r"(r[3]) : "r"(addr));
}

__device__ __forceinline__ void mma16816(float* c, const uint32_t* a,
                                         uint32_t b0, uint32_t b1) {
    asm volatile(
        "mma.sync.aligned.m16n8k16.row.col.f32.bf16.bf16.f32 "
        "{%0,%1,%2,%3}, {%4,%5,%6,%7}, {%8,%9}, {%0,%1,%2,%3};"
        : "+f"(c[0]), "+f"(c[1]), "+f"(c[2]), "+f"(c[3])
        : "r"(a[0]), "r"(a[1]), "r"(a[2]), "r"(a[3]), "r"(b0), "r"(b1));
}

__device__ __forceinline__ void cp16(uint32_t dst, const void* src) {
    asm volatile("cp.async.cg.shared.global [%0], [%1], 16;"
                 :: "r"(dst), "l"(src));
}
#define CP_COMMIT() asm volatile("cp.async.commit_group;" ::: "memory")

// smem regions per stage (32 KB): Ah, Al, Bh, Bl each 128x32 bf16 = 8 KB
#define R_AH 0u
#define R_AL 8192u
#define R_BH 16384u
#define R_BL 24576u
#define BUFB 32768u
#define NSTAGE 3
#define DSMEM_BYTES (NSTAGE * BUFB)

// ============================================================================
// small kernels
// ============================================================================
__global__ void zero_state_kernel() {
    int i = threadIdx.x;
    if (i < NEXP) { g_count[i] = 0; g_probsum[i] = 0.0f; }
}

// fp32 -> (bf16 hi, bf16 lo) planes, vectorized
__global__ __launch_bounds__(256) void split_kernel(
    const float* __restrict__ s, __nv_bfloat16* __restrict__ hp,
    __nv_bfloat16* __restrict__ lp, int n4)
{
    int i = blockIdx.x * blockDim.x + threadIdx.x;
    int st = gridDim.x * blockDim.x;
    for (; i < n4; i += st) {
        float4 v = ((const float4*)s)[i];
        __nv_bfloat16 h0 = __float2bfloat16(v.x);
        __nv_bfloat16 h1 = __float2bfloat16(v.y);
        __nv_bfloat16 h2 = __float2bfloat16(v.z);
        __nv_bfloat16 h3 = __float2bfloat16(v.w);
        __nv_bfloat162 hA, hB, lA, lB;
        hA.x = h0; hA.y = h1; hB.x = h2; hB.y = h3;
        lA.x = __float2bfloat16(v.x - __bfloat162float(h0));
        lA.y = __float2bfloat16(v.y - __bfloat162float(h1));
        lB.x = __float2bfloat16(v.z - __bfloat162float(h2));
        lB.y = __float2bfloat16(v.w - __bfloat162float(h3));
        ((__nv_bfloat162*)hp)[2 * i]     = hA;
        ((__nv_bfloat162*)hp)[2 * i + 1] = hB;
        ((__nv_bfloat162*)lp)[2 * i]     = lA;
        ((__nv_bfloat162*)lp)[2 * i + 1] = lB;
    }
}

// Router: one warp per token; fp64 dots for tie-robust top-k selection.
__global__ __launch_bounds__(256) void router_kernel(
    const float* __restrict__ x, const float* __restrict__ rw,
    const float* __restrict__ rb)
{
    __shared__ float bsum[NEXP];
    int tid = threadIdx.x;
    if (tid < NEXP) bsum[tid] = 0.0f;
    __syncthreads();

    int warp = tid >> 5, lane = tid & 31;
    int t = blockIdx.x * 8 + warp;

    double part[NEXP];
#pragma unroll
    for (int e = 0; e < NEXP; e++) part[e] = 0.0;

    const float* xr = x + (size_t)t * DMODEL;
    for (int d = lane * 4; d < DMODEL; d += 32 * 4) {
        float4 xv = *(const float4*)&xr[d];
#pragma unroll
        for (int e = 0; e < NEXP; e++) {
            float4 wv = *(const float4*)&rw[e * DMODEL + d];
            part[e] += (double)xv.x * wv.x + (double)xv.y * wv.y
                     + (double)xv.z * wv.z + (double)xv.w * wv.w;
        }
    }
#pragma unroll
    for (int e = 0; e < NEXP; e++) {
#pragma unroll
        for (int o = 16; o > 0; o >>= 1)
            part[e] += __shfl_xor_sync(0xffffffffu, part[e], o);
    }

    if (lane == 0) {
        float l[NEXP], m = -1e30f;
#pragma unroll
        for (int e = 0; e < NEXP; e++) { l[e] = (float)part[e] + rb[e]; m = fmaxf(m, l[e]); }
        float p[NEXP], s = 0.0f;
#pragma unroll
        for (int e = 0; e < NEXP; e++) { p[e] = expf(l[e] - m); s += p[e]; }
        float inv = 1.0f / s;
#pragma unroll
        for (int e = 0; e < NEXP; e++) p[e] *= inv;

        int i0 = 0;
#pragma unroll
        for (int e = 1; e < NEXP; e++) if (p[e] > p[i0]) i0 = e;
        int i1 = -1;
#pragma unroll
        for (int e = 0; e < NEXP; e++)
            if (e != i0 && (i1 < 0 || p[e] > p[i1])) i1 = e;

        float ws = p[i0] + p[i1];
        float w0 = p[i0] / ws, w1 = p[i1] / ws;

        int pos0 = atomicAdd(&g_count[i0], 1);
        g_token[i0 * NTOK + pos0] = t;
        int pos1 = atomicAdd(&g_count[i1], 1);
        g_token[i1 * NTOK + pos1] = t;

        g_ae[t * 2 + 0] = i0; g_ap[t * 2 + 0] = pos0; g_aw[t * 2 + 0] = w0;
        g_ae[t * 2 + 1] = i1; g_ap[t * 2 + 1] = pos1; g_aw[t * 2 + 1] = w1;

#pragma unroll
        for (int e = 0; e < NEXP; e++) atomicAdd(&bsum[e], p[e]);
    }
    __syncthreads();
    if (tid < NEXP) atomicAdd(&g_probsum[tid], bsum[tid]);
}

__global__ void prefix_loss_kernel(float* out, int out_size) {
    if (threadIdx.x == 0 && blockIdx.x == 0) {
        int b = 0;
        float loss = 0.0f;
#pragma unroll
        for (int e = 0; e < NEXP; e++) {
            g_base[e] = b;
            b += g_count[e];
            float usage = (float)g_count[e] / (float)(NTOK * 2);
            float meanp = g_probsum[e] / (float)NTOK;
            loss += usage * meanp;
        }
        out[out_size - 1] = 0.01f * (float)NEXP * loss;
    }
}

// out[t] = w0*y[row0] + w1*y[row1]  (deterministic combine; bias in y)
__global__ __launch_bounds__(256) void combine_kernel(float* __restrict__ out) {
    int t = blockIdx.x;
    int e0 = g_ae[t * 2 + 0], e1 = g_ae[t * 2 + 1];
    long r0 = g_base[e0] + g_ap[t * 2 + 0];
    long r1 = g_base[e1] + g_ap[t * 2 + 1];
    float w0 = g_aw[t * 2 + 0], w1 = g_aw[t * 2 + 1];
    int c = threadIdx.x * 4;
    float4 y0 = *(const float4*)&g_y[(size_t)r0 * DOUT + c];
    float4 y1 = *(const float4*)&g_y[(size_t)r1 * DOUT + c];
    float4 o;
    o.x = w0 * y0.x + w1 * y1.x;
    o.y = w0 * y0.y + w1 * y1.y;
    o.z = w0 * y0.z + w1 * y1.z;
    o.w = w0 * y0.w + w1 * y1.w;
    *(float4*)&out[(size_t)t * DOUT + c] = o;
}

// ============================================================================
// bf16-split tensor GEMM, cp.async 3-stage pipeline.
// GATHER=true : A = x planes (gathered rows), Out = relu(.+b1) -> g_hh/g_hl
// GATHER=false: A = g_h planes (dense rows),  Out = .+b2       -> g_y
// Tile 128(M) x 128(N), K-stage 32, 8 warps (2m x 4n), 64 fp32 acc/thread.
// ============================================================================
template <int KTOT, int NOUT, bool GATHER>
__global__ __launch_bounds__(256) void moe_gemm_kernel(const float* __restrict__ bias)
{
    int e   = blockIdx.z;
    int cnt = g_count[e];
    int m0  = blockIdx.x * 128;
    if (m0 >= cnt) return;
    int n0  = blockIdx.y * 128;
    int basee = g_base[e];

    const __nv_bfloat16* Ah = GATHER ? g_xh  : g_hh;
    const __nv_bfloat16* Al = GATHER ? g_xl  : g_hl;
    const __nv_bfloat16* Wh = GATHER ? g_w1h : g_w2h;
    const __nv_bfloat16* Wl = GATHER ? g_w1l : g_w2l;

    extern __shared__ char smem[];
    uint32_t sb = smem_u32(smem);

    int tid = threadIdx.x, wid = tid >> 5, lane = tid & 31;
    int wm = wid >> 2, wn = wid & 3;

    // ---------------- producer: 8 x 16B cp.async per thread per K-stage -----
    const __nv_bfloat16 *pah[2], *pal[2], *pbh[2], *pbl[2];
    uint32_t dsto[2];
    const int* toks = g_token + e * NTOK;
#pragma unroll
    for (int i = 0; i < 2; i++) {
        int cid = tid + i * 256;           // 0..511
        int row = cid >> 2, kc = cid & 3;  // 128 rows x 4 chunks of 8 bf16
        int gm = m0 + row;
        int cg = (gm < cnt) ? gm : (cnt - 1);
        size_t ar = GATHER ? (size_t)toks[cg] : (size_t)(basee + cg);
        pah[i] = Ah + ar * KTOT + kc * 8;
        pal[i] = Al + ar * KTOT + kc * 8;
        size_t br = (size_t)e * NOUT + (size_t)(n0 + row);
        pbh[i] = Wh + br * KTOT + kc * 8;
        pbl[i] = Wl + br * KTOT + kc * 8;
        dsto[i] = (uint32_t)((row << 6) + (((kc ^ ((row >> 1) & 3))) << 4));
    }

    auto produce = [&](int kt, int st) {
        uint32_t b = sb + (uint32_t)st * BUFB;
#pragma unroll
        for (int i = 0; i < 2; i++) {
            cp16(b + R_AH + dsto[i], pah[i] + kt * 32);
            cp16(b + R_AL + dsto[i], pal[i] + kt * 32);
            cp16(b + R_BH + dsto[i], pbh[i] + kt * 32);
            cp16(b + R_BL + dsto[i], pbl[i] + kt * 32);
        }
        CP_COMMIT();
    };

    // ---------------- consumer (ldmatrix) metadata ----------------
    int rloc  = ((lane >> 3) & 1) * 8 + (lane & 7);
    int cpart = (lane >> 4) & 1;
    uint32_t abase[4]; int amask[4];
#pragma unroll
    for (int i = 0; i < 4; i++) {
        int r = wm * 64 + i * 16 + rloc;
        abase[i] = (uint32_t)(r << 6);
        amask[i] = (r >> 1) & 3;
    }
    uint32_t bbase[2]; int bmask[2];
#pragma unroll
    for (int jj = 0; jj < 2; jj++) {
        int r = wn * 32 + jj * 16 + rloc;
        bbase[jj] = (uint32_t)(r << 6);
        bmask[jj] = (r >> 1) & 3;
    }

    float acc[4][4][4];
#pragma unroll
    for (int i = 0; i < 4; i++)
#pragma unroll
        for (int j = 0; j < 4; j++)
#pragma unroll
            for (int q = 0; q < 4; q++) acc[i][j][q] = 0.0f;

    const int KT = KTOT / 32;

    produce(0, 0);
    produce(1, 1);

    int sc = 0;
    for (int kt = 0; kt < KT; kt++) {
        if (kt + 1 < KT) asm volatile("cp.async.wait_group 1;" ::: "memory");
        else             asm volatile("cp.async.wait_group 0;" ::: "memory");
        __syncthreads();   // all threads' stage-sc copies visible; also fences
                           // last iteration's consumers before overwrite below
        if (kt + 2 < KT) {
            int sp = sc + 2; if (sp >= NSTAGE) sp -= NSTAGE;
            produce(kt + 2, sp);
        }

        uint32_t base = sb + (uint32_t)sc * BUFB;
#pragma unroll
        for (int kk = 0; kk < 2; kk++) {
            int ch = (kk << 1) | cpart;
            uint32_t bh[2][4], bl[2][4];
#pragma unroll
            for (int jj = 0; jj < 2; jj++) {
                uint32_t ad = base + R_BH + bbase[jj] + (uint32_t)((ch ^ bmask[jj]) << 4);
                ldsm4(bh[jj], ad);
                ldsm4(bl[jj], ad + (R_BL - R_BH));
            }
#pragma unroll
            for (int i = 0; i < 4; i++) {
                uint32_t ah4[4], al4[4];
                uint32_t ad = base + R_AH + abase[i] + (uint32_t)((ch ^ amask[i]) << 4);
                ldsm4(ah4, ad);
                ldsm4(al4, ad + (R_AL - R_AH));
#pragma unroll
                for (int j = 0; j < 4; j++) {
                    int jj = j >> 1, s = j & 1;
                    mma16816(acc[i][j], ah4, bh[jj][s], bh[jj][s + 2]);
                    mma16816(acc[i][j], ah4, bl[jj][s], bl[jj][s + 2]);
                    mma16816(acc[i][j], al4, bh[jj][s], bh[jj][s + 2]);
                }
            }
        }
        if (++sc == NSTAGE) sc = 0;
    }

    // ---------------- epilogue ----------------
    int r4 = lane >> 2, c2 = (lane & 3) * 2;
#pragma unroll
    for (int j = 0; j < 4; j++) {
        int col = n0 + wn * 32 + j * 8 + c2;
        float2 bj = *(const float2*)&bias[e * NOUT + col];
#pragma unroll
        for (int i = 0; i < 4; i++) {
            int gm0 = m0 + wm * 64 + i * 16 + r4;
            int gm1 = gm0 + 8;
#pragma unroll
            for (int half = 0; half < 2; half++) {
                int gm = half ? gm1 : gm0;
                if (gm >= cnt) continue;
                float vx = acc[i][j][half * 2 + 0] + bj.x;
                float vy = acc[i][j][half * 2 + 1] + bj.y;
                size_t off = (size_t)(basee + gm) * NOUT + col;
                if (GATHER) {
                    vx = fmaxf(vx, 0.0f);
                    vy = fmaxf(vy, 0.0f);
                    __nv_bfloat16 hx = __float2bfloat16(vx);
                    __nv_bfloat16 hy = __float2bfloat16(vy);
                    __nv_bfloat162 hv, lv;
                    hv.x = hx; hv.y = hy;
                    lv.x = __float2bfloat16(vx - __bfloat162float(hx));
                    lv.y = __float2bfloat16(vy - __bfloat162float(hy));
                    *(__nv_bfloat162*)&g_hh[off] = hv;
                    *(__nv_bfloat162*)&g_hl[off] = lv;
                } else {
                    float2 v; v.x = vx; v.y = vy;
                    *(float2*)&g_y[off] = v;
                }
            }
        }
    }
}

// ============================================================================
extern "C" void kernel_launch(void* const* d_in, const int* in_sizes, int n_in,
                              void* d_out, int out_size)
{
    const float* x  = (const float*)d_in[0];
    const float* rw = (const float*)d_in[1];
    const float* rb = (const float*)d_in[2];
    const float* w1 = (const float*)d_in[3];
    const float* b1 = (const float*)d_in[4];
    const float* w2 = (const float*)d_in[5];
    const float* b2 = (const float*)d_in[6];
    float* out = (float*)d_out;

    cudaFuncSetAttribute(moe_gemm_kernel<DMODEL, DHID, true>,
                         cudaFuncAttributeMaxDynamicSharedMemorySize, DSMEM_BYTES);
    cudaFuncSetAttribute(moe_gemm_kernel<DHID, DOUT, false>,
                         cudaFuncAttributeMaxDynamicSharedMemorySize, DSMEM_BYTES);

    __nv_bfloat16 *xh, *xl, *w1h, *w1l, *w2h, *w2l;
    cudaGetSymbolAddress((void**)&xh,  g_xh);
    cudaGetSymbolAddress((void**)&xl,  g_xl);
    cudaGetSymbolAddress((void**)&w1h, g_w1h);
    cudaGetSymbolAddress((void**)&w1l, g_w1l);
    cudaGetSymbolAddress((void**)&w2h, g_w2h);
    cudaGetSymbolAddress((void**)&w2l, g_w2l);

    zero_state_kernel<<<1, 32>>>();
    router_kernel<<<NTOK / 8, 256>>>(x, rw, rb);
    prefix_loss_kernel<<<1, 32>>>(out, out_size);

    split_kernel<<<2048, 256>>>(x,  xh,  xl,  NTOK * DMODEL / 4);
    split_kernel<<<4096, 256>>>(w1, w1h, w1l, NEXP * DHID * DMODEL / 4);
    split_kernel<<<4096, 256>>>(w2, w2h, w2l, NEXP * DOUT * DHID / 4);

    moe_gemm_kernel<DMODEL, DHID, true>
        <<<dim3(NTOK / 128, DHID / 128, NEXP), 256, DSMEM_BYTES>>>(b1);
    moe_gemm_kernel<DHID, DOUT, false>
        <<<dim3(NTOK / 128, DOUT / 128, NEXP), 256, DSMEM_BYTES>>>(b2);
    combine_kernel<<<NTOK, 256>>>(out);
}

// round 8
// speedup vs baseline: 1.0326x; 1.0326x over previous
#include <cuda_runtime.h>
#include <cuda_bf16.h>
#include <math.h>
#include <stdint.h>

// ============================================================================
// MoE (T=8192, D=1024, H=4096, O=1024, E=8, top-2)
// mma.sync m16n8k16 bf16 with 2-way operand split (3 MMAs) ~ fp32 accuracy.
// hi/lo planes fused into single arrays (+compile-time plane offset) to cut
// producer registers; GEMMs forced to 2 CTAs/SM. Plain sm_103 PTX only.
// ============================================================================

#define NTOK   8192
#define DMODEL 1024
#define DHID   4096
#define DOUT   1024
#define NEXP   8
#define MAXROWS (NTOK * 2)

#define XOFF  ((size_t)NTOK * DMODEL)
#define W1OFF ((size_t)NEXP * DHID * DMODEL)
#define W2OFF ((size_t)NEXP * DOUT * DHID)
#define HOFF  ((size_t)MAXROWS * DHID)

// -------------------- device scratch (no allocs allowed) --------------------
__device__ int   g_count[NEXP];
__device__ int   g_base[NEXP];
__device__ float g_probsum[NEXP];
__device__ int   g_token[NEXP * NTOK];
__device__ int   g_ae[NTOK * 2];
__device__ int   g_ap[NTOK * 2];
__device__ float g_aw[NTOK * 2];

__device__ __nv_bfloat16 g_xs [2 * XOFF];    // hi plane, then lo plane
__device__ __nv_bfloat16 g_w1s[2 * W1OFF];
__device__ __nv_bfloat16 g_w2s[2 * W2OFF];
__device__ __nv_bfloat16 g_hs [2 * HOFF];
__device__ float         g_y  [(size_t)MAXROWS * DOUT];

// -------------------- helpers --------------------
__device__ __forceinline__ uint32_t smem_u32(const void* p) {
    uint32_t a;
    asm("{ .reg .u64 t; cvta.to.shared.u64 t, %1; cvt.u32.u64 %0, t; }"
        : "=r"(a) : "l"(p));
    return a;
}

__device__ __forceinline__ void ldsm4(uint32_t* r, uint32_t addr) {
    asm volatile("ldmatrix.sync.aligned.m8n8.x4.shared.b16 {%0,%1,%2,%3}, [%4];"
                 : "=r"(r[0]), "=r"(r[1]), "=r"(r[2]), "=r"(r[3]) : "r"(addr));
}

__device__ __forceinline__ void mma16816(float* c, const uint32_t* a,
                                         uint32_t b0, uint32_t b1) {
    asm volatile(
        "mma.sync.aligned.m16n8k16.row.col.f32.bf16.bf16.f32 "
        "{%0,%1,%2,%3}, {%4,%5,%6,%7}, {%8,%9}, {%0,%1,%2,%3};"
        : "+f"(c[0]), "+f"(c[1]), "+f"(c[2]), "+f"(c[3])
        : "r"(a[0]), "r"(a[1]), "r"(a[2]), "r"(a[3]), "r"(b0), "r"(b1));
}

__device__ __forceinline__ void cp16(uint32_t dst, const void* src) {
    asm volatile("cp.async.cg.shared.global [%0], [%1], 16;"
                 :: "r"(dst), "l"(src));
}
#define CP_COMMIT() asm volatile("cp.async.commit_group;" ::: "memory")

// smem regions per stage (32 KB): Ah, Al, Bh, Bl each 128x32 bf16 = 8 KB
#define R_AH 0u
#define R_AL 8192u
#define R_BH 16384u
#define R_BL 24576u
#define BUFB 32768u
#define NSTAGE 3
#define DSMEM_BYTES (NSTAGE * BUFB)

// ============================================================================
// prep: zero router state + split x/w1/w2 into bf16 hi/lo planes (one launch)
// ============================================================================
__global__ __launch_bounds__(256) void prep_kernel(
    const float* __restrict__ x, const float* __restrict__ w1,
    const float* __restrict__ w2)
{
    long i = (long)blockIdx.x * 256 + threadIdx.x;
    if (i < NEXP) { g_count[i] = 0; g_probsum[i] = 0.0f; }

    const long n4x = (long)(XOFF / 4);
    const long n4w = (long)(W1OFF / 4);
    long total = n4x + 2 * n4w;
    long st = (long)gridDim.x * 256;
    for (long j = i; j < total; j += st) {
        const float* s; __nv_bfloat16 *hp, *lp; long k;
        if (j < n4x)            { s = x;  hp = g_xs;  lp = g_xs  + XOFF;  k = j; }
        else if (j < n4x + n4w) { s = w1; hp = g_w1s; lp = g_w1s + W1OFF; k = j - n4x; }
        else                    { s = w2; hp = g_w2s; lp = g_w2s + W2OFF; k = j - n4x - n4w; }
        float4 v = ((const float4*)s)[k];
        __nv_bfloat16 h0 = __float2bfloat16(v.x);
        __nv_bfloat16 h1 = __float2bfloat16(v.y);
        __nv_bfloat16 h2 = __float2bfloat16(v.z);
        __nv_bfloat16 h3 = __float2bfloat16(v.w);
        __nv_bfloat162 hA, hB, lA, lB;
        hA.x = h0; hA.y = h1; hB.x = h2; hB.y = h3;
        lA.x = __float2bfloat16(v.x - __bfloat162float(h0));
        lA.y = __float2bfloat16(v.y - __bfloat162float(h1));
        lB.x = __float2bfloat16(v.z - __bfloat162float(h2));
        lB.y = __float2bfloat16(v.w - __bfloat162float(h3));
        ((__nv_bfloat162*)hp)[2 * k]     = hA;
        ((__nv_bfloat162*)hp)[2 * k + 1] = hB;
        ((__nv_bfloat162*)lp)[2 * k]     = lA;
        ((__nv_bfloat162*)lp)[2 * k + 1] = lB;
    }
}

// ============================================================================
// Router: one warp per token; fp64 dots for tie-robust top-k selection.
// ============================================================================
__global__ __launch_bounds__(256) void router_kernel(
    const float* __restrict__ x, const float* __restrict__ rw,
    const float* __restrict__ rb)
{
    __shared__ float bsum[NEXP];
    int tid = threadIdx.x;
    if (tid < NEXP) bsum[tid] = 0.0f;
    __syncthreads();

    int warp = tid >> 5, lane = tid & 31;
    int t = blockIdx.x * 8 + warp;

    double part[NEXP];
#pragma unroll
    for (int e = 0; e < NEXP; e++) part[e] = 0.0;

    const float* xr = x + (size_t)t * DMODEL;
    for (int d = lane * 4; d < DMODEL; d += 32 * 4) {
        float4 xv = *(const float4*)&xr[d];
#pragma unroll
        for (int e = 0; e < NEXP; e++) {
            float4 wv = *(const float4*)&rw[e * DMODEL + d];
            part[e] += (double)xv.x * wv.x + (double)xv.y * wv.y
                     + (double)xv.z * wv.z + (double)xv.w * wv.w;
        }
    }
#pragma unroll
    for (int e = 0; e < NEXP; e++) {
#pragma unroll
        for (int o = 16; o > 0; o >>= 1)
            part[e] += __shfl_xor_sync(0xffffffffu, part[e], o);
    }

    if (lane == 0) {
        float l[NEXP], m = -1e30f;
#pragma unroll
        for (int e = 0; e < NEXP; e++) { l[e] = (float)part[e] + rb[e]; m = fmaxf(m, l[e]); }
        float p[NEXP], s = 0.0f;
#pragma unroll
        for (int e = 0; e < NEXP; e++) { p[e] = expf(l[e] - m); s += p[e]; }
        float inv = 1.0f / s;
#pragma unroll
        for (int e = 0; e < NEXP; e++) p[e] *= inv;

        int i0 = 0;
#pragma unroll
        for (int e = 1; e < NEXP; e++) if (p[e] > p[i0]) i0 = e;
        int i1 = -1;
#pragma unroll
        for (int e = 0; e < NEXP; e++)
            if (e != i0 && (i1 < 0 || p[e] > p[i1])) i1 = e;

        float ws = p[i0] + p[i1];
        float w0 = p[i0] / ws, w1 = p[i1] / ws;

        int pos0 = atomicAdd(&g_count[i0], 1);
        g_token[i0 * NTOK + pos0] = t;
        int pos1 = atomicAdd(&g_count[i1], 1);
        g_token[i1 * NTOK + pos1] = t;

        g_ae[t * 2 + 0] = i0; g_ap[t * 2 + 0] = pos0; g_aw[t * 2 + 0] = w0;
        g_ae[t * 2 + 1] = i1; g_ap[t * 2 + 1] = pos1; g_aw[t * 2 + 1] = w1;

#pragma unroll
        for (int e = 0; e < NEXP; e++) atomicAdd(&bsum[e], p[e]);
    }
    __syncthreads();
    if (tid < NEXP) atomicAdd(&g_probsum[tid], bsum[tid]);
}

__global__ void prefix_loss_kernel(float* out, int out_size) {
    if (threadIdx.x == 0 && blockIdx.x == 0) {
        int b = 0;
        float loss = 0.0f;
#pragma unroll
        for (int e = 0; e < NEXP; e++) {
            g_base[e] = b;
            b += g_count[e];
            float usage = (float)g_count[e] / (float)(NTOK * 2);
            float meanp = g_probsum[e] / (float)NTOK;
            loss += usage * meanp;
        }
        out[out_size - 1] = 0.01f * (float)NEXP * loss;
    }
}

// out[t] = w0*y[row0] + w1*y[row1]  (deterministic combine; bias in y)
__global__ __launch_bounds__(256) void combine_kernel(float* __restrict__ out) {
    int t = blockIdx.x;
    int e0 = g_ae[t * 2 + 0], e1 = g_ae[t * 2 + 1];
    long r0 = g_base[e0] + g_ap[t * 2 + 0];
    long r1 = g_base[e1] + g_ap[t * 2 + 1];
    float w0 = g_aw[t * 2 + 0], w1 = g_aw[t * 2 + 1];
    int c = threadIdx.x * 4;
    float4 y0 = *(const float4*)&g_y[(size_t)r0 * DOUT + c];
    float4 y1 = *(const float4*)&g_y[(size_t)r1 * DOUT + c];
    float4 o;
    o.x = w0 * y0.x + w1 * y1.x;
    o.y = w0 * y0.y + w1 * y1.y;
    o.z = w0 * y0.z + w1 * y1.z;
    o.w = w0 * y0.w + w1 * y1.w;
    *(float4*)&out[(size_t)t * DOUT + c] = o;
}

// ============================================================================
// bf16-split tensor GEMM, cp.async 3-stage pipeline, 2 CTAs/SM enforced.
// GATHER=true : A = x planes (gathered rows), Out = relu(.+b1) -> g_hs planes
// GATHER=false: A = g_hs planes (dense rows), Out = .+b2       -> g_y
// Tile 128(M) x 128(N), K-stage 32, 8 warps (2m x 4n), 64 fp32 acc/thread.
// AOFF/WOFF: compile-time element offset from hi plane to lo plane.
// ============================================================================
template <int KTOT, int NOUT, bool GATHER, size_t AOFF, size_t WOFF>
__global__ __launch_bounds__(256, 2) void moe_gemm_kernel(const float* __restrict__ bias)
{
    int e   = blockIdx.z;
    int cnt = g_count[e];
    int m0  = blockIdx.x * 128;
    if (m0 >= cnt) return;
    int n0  = blockIdx.y * 128;
    int basee = g_base[e];

    const __nv_bfloat16* A = GATHER ? g_xs  : g_hs;
    const __nv_bfloat16* W = GATHER ? g_w1s : g_w2s;

    extern __shared__ char smem[];
    uint32_t sb = smem_u32(smem);

    int tid = threadIdx.x, wid = tid >> 5, lane = tid & 31;
    int wm = wid >> 2, wn = wid & 3;

    // ---------------- producer: 8 x 16B cp.async per thread per K-stage -----
    const __nv_bfloat16 *pa[2], *pb[2];
    uint32_t dsto[2];
    const int* toks = g_token + e * NTOK;
#pragma unroll
    for (int i = 0; i < 2; i++) {
        int cid = tid + i * 256;           // 0..511
        int row = cid >> 2, kc = cid & 3;  // 128 rows x 4 chunks of 8 bf16
        int gm = m0 + row;
        int cg = (gm < cnt) ? gm : (cnt - 1);
        size_t ar = GATHER ? (size_t)toks[cg] : (size_t)(basee + cg);
        pa[i] = A + ar * KTOT + kc * 8;
        pb[i] = W + ((size_t)e * NOUT + (size_t)(n0 + row)) * KTOT + kc * 8;
        dsto[i] = (uint32_t)((row << 6) + (((kc ^ ((row >> 1) & 3))) << 4));
    }

    auto produce = [&](int kt, int st) {
        uint32_t b = sb + (uint32_t)st * BUFB;
#pragma unroll
        for (int i = 0; i < 2; i++) {
            cp16(b + R_AH + dsto[i], pa[i] + kt * 32);
            cp16(b + R_AL + dsto[i], pa[i] + kt * 32 + AOFF);
            cp16(b + R_BH + dsto[i], pb[i] + kt * 32);
            cp16(b + R_BL + dsto[i], pb[i] + kt * 32 + WOFF);
        }
        CP_COMMIT();
    };

    // ---------------- consumer (ldmatrix) metadata ----------------
    int rloc  = ((lane >> 3) & 1) * 8 + (lane & 7);
    int cpart = (lane >> 4) & 1;
    uint32_t abase[4]; int amask[4];
#pragma unroll
    for (int i = 0; i < 4; i++) {
        int r = wm * 64 + i * 16 + rloc;
        abase[i] = (uint32_t)(r << 6);
        amask[i] = (r >> 1) & 3;
    }
    uint32_t bbase[2]; int bmask[2];
#pragma unroll
    for (int jj = 0; jj < 2; jj++) {
        int r = wn * 32 + jj * 16 + rloc;
        bbase[jj] = (uint32_t)(r << 6);
        bmask[jj] = (r >> 1) & 3;
    }

    float acc[4][4][4];
#pragma unroll
    for (int i = 0; i < 4; i++)
#pragma unroll
        for (int j = 0; j < 4; j++)
#pragma unroll
            for (int q = 0; q < 4; q++) acc[i][j][q] = 0.0f;

    const int KT = KTOT / 32;

    produce(0, 0);
    produce(1, 1);

    int sc = 0;
    for (int kt = 0; kt < KT; kt++) {
        if (kt + 1 < KT) asm volatile("cp.async.wait_group 1;" ::: "memory");
        else             asm volatile("cp.async.wait_group 0;" ::: "memory");
        __syncthreads();   // stage-sc copies visible; also fences last
                           // iteration's consumers before the overwrite below
        if (kt + 2 < KT) {
            int sp = sc + 2; if (sp >= NSTAGE) sp -= NSTAGE;
            produce(kt + 2, sp);
        }

        uint32_t base = sb + (uint32_t)sc * BUFB;
#pragma unroll
        for (int kk = 0; kk < 2; kk++) {
            int ch = (kk << 1) | cpart;
            uint32_t bh[2][4], bl[2][4];
#pragma unroll
            for (int jj = 0; jj < 2; jj++) {
                uint32_t ad = base + R_BH + bbase[jj] + (uint32_t)((ch ^ bmask[jj]) << 4);
                ldsm4(bh[jj], ad);
                ldsm4(bl[jj], ad + (R_BL - R_BH));
            }
#pragma unroll
            for (int i = 0; i < 4; i++) {
                uint32_t ah4[4], al4[4];
                uint32_t ad = base + R_AH + abase[i] + (uint32_t)((ch ^ amask[i]) << 4);
                ldsm4(ah4, ad);
                ldsm4(al4, ad + (R_AL - R_AH));
#pragma unroll
                for (int j = 0; j < 4; j++) {
                    int jj = j >> 1, s = j & 1;
                    mma16816(acc[i][j], ah4, bh[jj][s], bh[jj][s + 2]);
                    mma16816(acc[i][j], ah4, bl[jj][s], bl[jj][s + 2]);
                    mma16816(acc[i][j], al4, bh[jj][s], bh[jj][s + 2]);
                }
            }
        }
        if (++sc == NSTAGE) sc = 0;
    }

    // ---------------- epilogue ----------------
    int r4 = lane >> 2, c2 = (lane & 3) * 2;
#pragma unroll
    for (int j = 0; j < 4; j++) {
        int col = n0 + wn * 32 + j * 8 + c2;
        float2 bj = *(const float2*)&bias[e * NOUT + col];
#pragma unroll
        for (int i = 0; i < 4; i++) {
            int gm0 = m0 + wm * 64 + i * 16 + r4;
            int gm1 = gm0 + 8;
#pragma unroll
            for (int half = 0; half < 2; half++) {
                int gm = half ? gm1 : gm0;
                if (gm >= cnt) continue;
                float vx = acc[i][j][half * 2 + 0] + bj.x;
                float vy = acc[i][j][half * 2 + 1] + bj.y;
                size_t off = (size_t)(basee + gm) * NOUT + col;
                if (GATHER) {
                    vx = fmaxf(vx, 0.0f);
                    vy = fmaxf(vy, 0.0f);
                    __nv_bfloat16 hx = __float2bfloat16(vx);
                    __nv_bfloat16 hy = __float2bfloat16(vy);
                    __nv_bfloat162 hv, lv;
                    hv.x = hx; hv.y = hy;
                    lv.x = __float2bfloat16(vx - __bfloat162float(hx));
                    lv.y = __float2bfloat16(vy - __bfloat162float(hy));
                    *(__nv_bfloat162*)&g_hs[off] = hv;
                    *(__nv_bfloat162*)&g_hs[off + HOFF] = lv;
                } else {
                    float2 v; v.x = vx; v.y = vy;
                    *(float2*)&g_y[off] = v;
                }
            }
        }
    }
}

// ============================================================================
extern "C" void kernel_launch(void* const* d_in, const int* in_sizes, int n_in,
                              void* d_out, int out_size)
{
    const float* x  = (const float*)d_in[0];
    const float* rw = (const float*)d_in[1];
    const float* rb = (const float*)d_in[2];
    const float* w1 = (const float*)d_in[3];
    const float* b1 = (const float*)d_in[4];
    const float* w2 = (const float*)d_in[5];
    const float* b2 = (const float*)d_in[6];
    float* out = (float*)d_out;

    cudaFuncSetAttribute((const void*)moe_gemm_kernel<DMODEL, DHID, true,  XOFF, W1OFF>,
                         cudaFuncAttributeMaxDynamicSharedMemorySize, DSMEM_BYTES);
    cudaFuncSetAttribute((const void*)moe_gemm_kernel<DHID, DOUT, false, HOFF, W2OFF>,
                         cudaFuncAttributeMaxDynamicSharedMemorySize, DSMEM_BYTES);

    // launch 0: zero state + all hi/lo splits
    prep_kernel<<<4096, 256>>>(x, w1, w2);
    // launch 1-2: routing + prefix/loss
    router_kernel<<<NTOK / 8, 256>>>(x, rw, rb);
    prefix_loss_kernel<<<1, 32>>>(out, out_size);
    // launch 3: gemm1 (profiler slot)
    moe_gemm_kernel<DMODEL, DHID, true, XOFF, W1OFF>
        <<<dim3(NTOK / 128, DHID / 128, NEXP), 256, DSMEM_BYTES>>>(b1);
    // launch 4: gemm2
    moe_gemm_kernel<DHID, DOUT, false, HOFF, W2OFF>
        <<<dim3(NTOK / 128, DOUT / 128, NEXP), 256, DSMEM_BYTES>>>(b2);
    // launch 5: combine
    combine_kernel<<<NTOK, 256>>>(out);
}